// round 1
// baseline (speedup 1.0000x reference)
#include <cuda_runtime.h>
#include <cuda_bf16.h>
#include <math.h>

#define MAXN 50048          // cap on nodes (actual 50000)
#define INDIM 128
#define NH 8
#define OD 16
#define OCOLS 272           // 128 K + 128 V + 16 Qsum

// ---- device scratch (no allocations allowed) ----
__device__ float g_K [MAXN * 128];   // K projections  [N,128]
__device__ float g_V [MAXN * 128];   // V projections  [N,128]
__device__ float g_Qs[MAXN * 16];    // Qsum           [N,16]
__device__ float g_wV[MAXN * 128];   // scatter accum  [N,H,16]
__device__ float g_z [MAXN * 8];     // scatter accum  [N,H]
__device__ float g_W [OCOLS * 128];  // combined weights: Kw | Vw | Qsw_reduced
__device__ float g_b [OCOLS];        // combined bias

// ------------------------------------------------------------------
// Kernel 0: assemble combined weight matrix; reduce Q weights over heads
// ------------------------------------------------------------------
__global__ void prep_kernel(const float* __restrict__ Qw, const float* __restrict__ Qb,
                            const float* __restrict__ Kw, const float* __restrict__ Kb,
                            const float* __restrict__ Vw, const float* __restrict__ Vb)
{
    int t = blockIdx.x * blockDim.x + threadIdx.x;
    if (t < 128 * 128) {
        g_W[t]             = Kw[t];
        g_W[128 * 128 + t] = Vw[t];
    }
    if (t < 16 * 128) {
        int d = t / 128, c = t % 128;
        float s = 0.f;
        #pragma unroll
        for (int hh = 0; hh < NH; hh++) s += Qw[(hh * OD + d) * 128 + c];
        g_W[256 * 128 + t] = s;
    }
    if (t < 128) { g_b[t] = Kb[t]; g_b[128 + t] = Vb[t]; }
    if (t < 16) {
        float s = 0.f;
        #pragma unroll
        for (int hh = 0; hh < NH; hh++) s += Qb[hh * OD + t];
        g_b[256 + t] = s;
    }
}

// ------------------------------------------------------------------
// Kernel 1: zero accumulators
// ------------------------------------------------------------------
__global__ void zero_kernel(int N)
{
    int t = blockIdx.x * blockDim.x + threadIdx.x;       // float4 granularity
    int nWV = N * 32;                                    // N*128 floats / 4
    if (t < nWV) reinterpret_cast<float4*>(g_wV)[t] = make_float4(0.f, 0.f, 0.f, 0.f);
    if (t < N * 2) reinterpret_cast<float4*>(g_z)[t] = make_float4(0.f, 0.f, 0.f, 0.f);
}

// ------------------------------------------------------------------
// Kernel 2: fused projection GEMM  C[N, 272] = h[N,128] @ g_W^T + g_b
// classic 64x64 tile, 4x4 micro-tile, fp32 FFMA
// ------------------------------------------------------------------
#define BM 64
#define BN 64
#define BK 16
__global__ __launch_bounds__(256) void gemm_kernel(const float* __restrict__ h, int N)
{
    __shared__ float As[BK][BM + 4];
    __shared__ float Bs[BK][BN + 4];

    int tid = threadIdx.x;
    int tx = tid & 15;          // col group
    int ty = tid >> 4;          // row group
    int n0 = blockIdx.x * BM;
    int o0 = blockIdx.y * BN;

    float acc[4][4];
    #pragma unroll
    for (int i = 0; i < 4; i++)
        #pragma unroll
        for (int j = 0; j < 4; j++) acc[i][j] = 0.f;

    for (int k0 = 0; k0 < 128; k0 += BK) {
        #pragma unroll
        for (int t = tid; t < BM * BK; t += 256) {
            int i = t >> 4, kk = t & 15;
            int n = n0 + i;
            As[kk][i] = (n < N) ? h[n * 128 + k0 + kk] : 0.f;
        }
        #pragma unroll
        for (int t = tid; t < BN * BK; t += 256) {
            int j = t >> 4, kk = t & 15;
            int o = o0 + j;
            Bs[kk][j] = (o < OCOLS) ? g_W[o * 128 + k0 + kk] : 0.f;
        }
        __syncthreads();

        #pragma unroll
        for (int kk = 0; kk < BK; kk++) {
            float a[4], b[4];
            #pragma unroll
            for (int i = 0; i < 4; i++) a[i] = As[kk][ty * 4 + i];
            #pragma unroll
            for (int j = 0; j < 4; j++) b[j] = Bs[kk][tx * 4 + j];
            #pragma unroll
            for (int i = 0; i < 4; i++)
                #pragma unroll
                for (int j = 0; j < 4; j++) acc[i][j] = fmaf(a[i], b[j], acc[i][j]);
        }
        __syncthreads();
    }

    #pragma unroll
    for (int i = 0; i < 4; i++) {
        int n = n0 + ty * 4 + i;
        if (n >= N) continue;
        #pragma unroll
        for (int j = 0; j < 4; j++) {
            int o = o0 + tx * 4 + j;
            if (o >= OCOLS) continue;
            float c = acc[i][j] + g_b[o];
            if      (o < 128) g_K [n * 128 + o]        = c;
            else if (o < 256) g_V [n * 128 + (o - 128)] = c;
            else              g_Qs[n * 16  + (o - 256)] = c;
        }
    }
}

// ------------------------------------------------------------------
// Kernel 3: edge scatter. One warp per edge.
//   lane l covers elements [4l, 4l+4) of the 128-wide K/V rows; head = l/4
// ------------------------------------------------------------------
__global__ __launch_bounds__(256) void edge_kernel(const int* __restrict__ src,
                                                   const int* __restrict__ dst,
                                                   int nE)
{
    int w    = (blockIdx.x * blockDim.x + threadIdx.x) >> 5;
    int lane = threadIdx.x & 31;
    if (w >= nE) return;

    int s = src[w];
    int d = dst[w];

    const float4 k4 = *reinterpret_cast<const float4*>(g_K  + s * 128 + lane * 4);
    const float4 q4 = *reinterpret_cast<const float4*>(g_Qs + d * 16  + (lane & 3) * 4);

    float p = k4.x * q4.x + k4.y * q4.y + k4.z * q4.z + k4.w * q4.w;
    p += __shfl_xor_sync(0xffffffffu, p, 1);
    p += __shfl_xor_sync(0xffffffffu, p, 2);

    float sc = expf(fminf(fmaxf(p * 0.25f, -5.f), 5.f));   // 1/sqrt(16) = 0.25

    const float4 v4 = *reinterpret_cast<const float4*>(g_V + s * 128 + lane * 4);
    float* wvp = g_wV + d * 128 + lane * 4;
    asm volatile("red.global.add.v4.f32 [%0], {%1,%2,%3,%4};"
                 :: "l"(wvp), "f"(v4.x * sc), "f"(v4.y * sc), "f"(v4.z * sc), "f"(v4.w * sc)
                 : "memory");

    if ((lane & 3) == 0)
        atomicAdd(g_z + d * 8 + (lane >> 2), sc);
}

// ------------------------------------------------------------------
// Kernel 4: finalize. One warp per node: add self-loop, divide by z,
//            mean over heads, write out[N,16].
// ------------------------------------------------------------------
__global__ __launch_bounds__(256) void final_kernel(float* __restrict__ out, int N)
{
    int n    = (blockIdx.x * blockDim.x + threadIdx.x) >> 5;
    int lane = threadIdx.x & 31;
    if (n >= N) return;

    const float4 k4 = *reinterpret_cast<const float4*>(g_K  + n * 128 + lane * 4);
    const float4 q4 = *reinterpret_cast<const float4*>(g_Qs + n * 16  + (lane & 3) * 4);

    float p = k4.x * q4.x + k4.y * q4.y + k4.z * q4.z + k4.w * q4.w;
    p += __shfl_xor_sync(0xffffffffu, p, 1);
    p += __shfl_xor_sync(0xffffffffu, p, 2);
    float sc = expf(fminf(fmaxf(p * 0.25f, -5.f), 5.f));

    int hd = lane >> 2;
    const float4 v4 = *reinterpret_cast<const float4*>(g_V  + n * 128 + lane * 4);
    float4 wv       = *reinterpret_cast<const float4*>(g_wV + n * 128 + lane * 4);
    wv.x += v4.x * sc; wv.y += v4.y * sc; wv.z += v4.z * sc; wv.w += v4.w * sc;

    float z = g_z[n * 8 + hd] + sc;
    float inv = 0.125f / z;         // divide by z and mean over 8 heads
    wv.x *= inv; wv.y *= inv; wv.z *= inv; wv.w *= inv;

    // sum across the 8 heads: lanes with equal (lane & 3) hold the same 4 out dims
    #pragma unroll
    for (int m = 4; m < 32; m <<= 1) {
        wv.x += __shfl_xor_sync(0xffffffffu, wv.x, m);
        wv.y += __shfl_xor_sync(0xffffffffu, wv.y, m);
        wv.z += __shfl_xor_sync(0xffffffffu, wv.z, m);
        wv.w += __shfl_xor_sync(0xffffffffu, wv.w, m);
    }

    if (lane < 4)
        *reinterpret_cast<float4*>(out + n * 16 + lane * 4) = wv;
}

// ------------------------------------------------------------------
extern "C" void kernel_launch(void* const* d_in, const int* in_sizes, int n_in,
                              void* d_out, int out_size)
{
    const float* h  = (const float*)d_in[0];
    const float* Qw = (const float*)d_in[1];
    const float* Qb = (const float*)d_in[2];
    const float* Kw = (const float*)d_in[3];
    const float* Kb = (const float*)d_in[4];
    const float* Vw = (const float*)d_in[5];
    const float* Vb = (const float*)d_in[6];
    const int*  src = (const int*) d_in[7];
    const int*  dst = (const int*) d_in[8];
    float* out = (float*)d_out;

    int N  = in_sizes[0] / INDIM;   // 50000
    int nE = in_sizes[7];           // 1600000

    // 0. assemble combined weights
    prep_kernel<<<(128 * 128 + 255) / 256, 256>>>(Qw, Qb, Kw, Kb, Vw, Vb);

    // 1. zero accumulators (float4 granularity)
    zero_kernel<<<(N * 32 + 255) / 256, 256>>>(N);

    // 2. fused projection GEMM -> g_K, g_V, g_Qs
    dim3 ggrid((N + BM - 1) / BM, (OCOLS + BN - 1) / BN);
    gemm_kernel<<<ggrid, 256>>>(h, N);

    // 3. edge scatter (warp per edge)
    int eblocks = (nE + 7) / 8;     // 8 warps per 256-thread block
    edge_kernel<<<eblocks, 256>>>(src, dst, nE);

    // 4. finalize (warp per node): self-loop + normalize + head mean
    int fblocks = (N + 7) / 8;
    final_kernel<<<fblocks, 256>>>(out, N);
}

// round 3
// speedup vs baseline: 1.8639x; 1.8639x over previous
#include <cuda_runtime.h>
#include <cuda_bf16.h>
#include <math.h>

#define MAXN 50048
#define INDIM 128
#define NH 8
#define OD 16
#define OCOLS 272           // 128 K + 128 V + 16 Qsum

// ---- device scratch ----
__device__ float g_K [MAXN * 128];
__device__ float g_V [MAXN * 128];
__device__ float g_Qs[MAXN * 16];
__device__ float g_wV[MAXN * 128];
__device__ float g_z [MAXN * 8];
__device__ float g_W [384 * 128];    // padded to grid multiple; cols 272..383 unused
__device__ float g_b [OCOLS];

// ------------------------------------------------------------------
// Kernel 0: assemble combined weights
// ------------------------------------------------------------------
__global__ void prep_kernel(const float* __restrict__ Qw, const float* __restrict__ Qb,
                            const float* __restrict__ Kw, const float* __restrict__ Kb,
                            const float* __restrict__ Vw, const float* __restrict__ Vb)
{
    int t = blockIdx.x * blockDim.x + threadIdx.x;
    if (t < 128 * 128) {
        g_W[t]             = Kw[t];
        g_W[128 * 128 + t] = Vw[t];
    }
    if (t < 16 * 128) {
        int d = t / 128, c = t % 128;
        float s = 0.f;
        #pragma unroll
        for (int hh = 0; hh < NH; hh++) s += Qw[(hh * OD + d) * 128 + c];
        g_W[256 * 128 + t] = s;
    }
    if (t >= 16 * 128 && t < 128 * 128) g_W[256 * 128 + t] = 0.f;  // pad cols
    if (t < 128) { g_b[t] = Kb[t]; g_b[128 + t] = Vb[t]; }
    if (t < 16) {
        float s = 0.f;
        #pragma unroll
        for (int hh = 0; hh < NH; hh++) s += Qb[hh * OD + t];
        g_b[256 + t] = s;
    }
}

// ------------------------------------------------------------------
// Kernel 1: zero accumulators
// ------------------------------------------------------------------
__global__ void zero_kernel(int N)
{
    int t = blockIdx.x * blockDim.x + threadIdx.x;
    int nWV = N * 32;
    if (t < nWV) reinterpret_cast<float4*>(g_wV)[t] = make_float4(0.f, 0.f, 0.f, 0.f);
    if (t < N * 2) reinterpret_cast<float4*>(g_z)[t] = make_float4(0.f, 0.f, 0.f, 0.f);
}

// ------------------------------------------------------------------
// Kernel 2: GEMM  C[N, 272] = h[N,128] @ g_W^T + g_b
// 128x128 tile, BK=8, 256 threads, 8x8 micro-tile in split-4 layout
// ------------------------------------------------------------------
#define BM 128
#define BN 128
#define BK 8
__global__ __launch_bounds__(256) void gemm_kernel(const float* __restrict__ h, int N)
{
    __shared__ float As[BK][BM + 4];
    __shared__ float Bs[BK][BN + 4];

    int tid = threadIdx.x;
    int tx = tid & 15;           // 0..15
    int ty = tid >> 4;           // 0..15
    int n0 = blockIdx.x * BM;
    int o0 = blockIdx.y * BN;

    // load mapping: each thread loads one float4 along K for A and one for B
    int lrow = tid >> 1;             // 0..127
    int lk   = (tid & 1) * 4;        // 0 or 4

    float acc[8][8];
    #pragma unroll
    for (int i = 0; i < 8; i++)
        #pragma unroll
        for (int j = 0; j < 8; j++) acc[i][j] = 0.f;

    int an = n0 + lrow; if (an >= N) an = N - 1;        // clamp (stores guarded)
    const float* aptr = h + an * 128 + lk;
    const float* bptr = g_W + (o0 + lrow) * 128 + lk;   // g_W padded to 384 rows

    for (int k0 = 0; k0 < 128; k0 += BK) {
        float4 av = *reinterpret_cast<const float4*>(aptr + k0);
        float4 bv = *reinterpret_cast<const float4*>(bptr + k0);
        As[lk + 0][lrow] = av.x; As[lk + 1][lrow] = av.y;
        As[lk + 2][lrow] = av.z; As[lk + 3][lrow] = av.w;
        Bs[lk + 0][lrow] = bv.x; Bs[lk + 1][lrow] = bv.y;
        Bs[lk + 2][lrow] = bv.z; Bs[lk + 3][lrow] = bv.w;
        __syncthreads();

        #pragma unroll
        for (int kk = 0; kk < BK; kk++) {
            float a[8], b[8];
            float4 a0 = *reinterpret_cast<const float4*>(&As[kk][ty * 4]);
            float4 a1 = *reinterpret_cast<const float4*>(&As[kk][64 + ty * 4]);
            float4 b0 = *reinterpret_cast<const float4*>(&Bs[kk][tx * 4]);
            float4 b1 = *reinterpret_cast<const float4*>(&Bs[kk][64 + tx * 4]);
            a[0]=a0.x; a[1]=a0.y; a[2]=a0.z; a[3]=a0.w;
            a[4]=a1.x; a[5]=a1.y; a[6]=a1.z; a[7]=a1.w;
            b[0]=b0.x; b[1]=b0.y; b[2]=b0.z; b[3]=b0.w;
            b[4]=b1.x; b[5]=b1.y; b[6]=b1.z; b[7]=b1.w;
            #pragma unroll
            for (int i = 0; i < 8; i++)
                #pragma unroll
                for (int j = 0; j < 8; j++) acc[i][j] = fmaf(a[i], b[j], acc[i][j]);
        }
        __syncthreads();
    }

    #pragma unroll
    for (int i = 0; i < 8; i++) {
        int n = n0 + ((i < 4) ? (ty * 4 + i) : (64 + ty * 4 + i - 4));
        if (n >= N) continue;
        #pragma unroll
        for (int j = 0; j < 8; j++) {
            int o = o0 + ((j < 4) ? (tx * 4 + j) : (64 + tx * 4 + j - 4));
            if (o >= OCOLS) continue;
            float c = acc[i][j] + g_b[o];
            if      (o < 128) g_K [n * 128 + o]         = c;
            else if (o < 256) g_V [n * 128 + (o - 128)] = c;
            else              g_Qs[n * 16  + (o - 256)] = c;
        }
    }
}

// ------------------------------------------------------------------
// Kernel 3: edge scatter. One warp per EPW edges (ILP batching).
// ------------------------------------------------------------------
#define EPW 4
__global__ __launch_bounds__(256) void edge_kernel(const int* __restrict__ src,
                                                   const int* __restrict__ dst,
                                                   int nE)
{
    int w    = (blockIdx.x * blockDim.x + threadIdx.x) >> 5;
    int lane = threadIdx.x & 31;
    int e0 = w * EPW;
    if (e0 >= nE) return;

    int s[EPW], d[EPW];
    if (e0 + EPW <= nE) {
        int4 sv = *reinterpret_cast<const int4*>(src + e0);
        int4 dv = *reinterpret_cast<const int4*>(dst + e0);
        s[0]=sv.x; s[1]=sv.y; s[2]=sv.z; s[3]=sv.w;
        d[0]=dv.x; d[1]=dv.y; d[2]=dv.z; d[3]=dv.w;
    } else {
        #pragma unroll
        for (int i = 0; i < EPW; i++) {
            int e = min(e0 + i, nE - 1);
            s[i] = __ldg(src + e);
            d[i] = __ldg(dst + e);
        }
    }

    // front-batch all gathers for MLP
    float4 k4[EPW], q4[EPW], v4[EPW];
    #pragma unroll
    for (int i = 0; i < EPW; i++)
        k4[i] = *reinterpret_cast<const float4*>(g_K  + s[i] * 128 + lane * 4);
    #pragma unroll
    for (int i = 0; i < EPW; i++)
        q4[i] = *reinterpret_cast<const float4*>(g_Qs + d[i] * 16  + (lane & 3) * 4);
    #pragma unroll
    for (int i = 0; i < EPW; i++)
        v4[i] = *reinterpret_cast<const float4*>(g_V  + s[i] * 128 + lane * 4);

    float sc[EPW];
    #pragma unroll
    for (int i = 0; i < EPW; i++) {
        float p = k4[i].x * q4[i].x + k4[i].y * q4[i].y
                + k4[i].z * q4[i].z + k4[i].w * q4[i].w;
        p += __shfl_xor_sync(0xffffffffu, p, 1);
        p += __shfl_xor_sync(0xffffffffu, p, 2);
        sc[i] = __expf(fminf(fmaxf(p * 0.25f, -5.f), 5.f));
    }

    #pragma unroll
    for (int i = 0; i < EPW; i++) {
        if (e0 + i >= nE) break;
        float* wvp = g_wV + d[i] * 128 + lane * 4;
        asm volatile("red.global.add.v4.f32 [%0], {%1,%2,%3,%4};"
                     :: "l"(wvp), "f"(v4[i].x * sc[i]), "f"(v4[i].y * sc[i]),
                        "f"(v4[i].z * sc[i]), "f"(v4[i].w * sc[i])
                     : "memory");
        if ((lane & 3) == 0)
            atomicAdd(g_z + d[i] * 8 + (lane >> 2), sc[i]);
    }
}

// ------------------------------------------------------------------
// Kernel 4: finalize (warp per node)
// ------------------------------------------------------------------
__global__ __launch_bounds__(256) void final_kernel(float* __restrict__ out, int N)
{
    int n    = (blockIdx.x * blockDim.x + threadIdx.x) >> 5;
    int lane = threadIdx.x & 31;
    if (n >= N) return;

    const float4 k4 = *reinterpret_cast<const float4*>(g_K  + n * 128 + lane * 4);
    const float4 q4 = *reinterpret_cast<const float4*>(g_Qs + n * 16  + (lane & 3) * 4);

    float p = k4.x * q4.x + k4.y * q4.y + k4.z * q4.z + k4.w * q4.w;
    p += __shfl_xor_sync(0xffffffffu, p, 1);
    p += __shfl_xor_sync(0xffffffffu, p, 2);
    float sc = __expf(fminf(fmaxf(p * 0.25f, -5.f), 5.f));

    int hd = lane >> 2;
    const float4 v4 = *reinterpret_cast<const float4*>(g_V  + n * 128 + lane * 4);
    float4 wv       = *reinterpret_cast<const float4*>(g_wV + n * 128 + lane * 4);
    wv.x += v4.x * sc; wv.y += v4.y * sc; wv.z += v4.z * sc; wv.w += v4.w * sc;

    float z = g_z[n * 8 + hd] + sc;
    float inv = 0.125f / z;
    wv.x *= inv; wv.y *= inv; wv.z *= inv; wv.w *= inv;

    #pragma unroll
    for (int m = 4; m < 32; m <<= 1) {
        wv.x += __shfl_xor_sync(0xffffffffu, wv.x, m);
        wv.y += __shfl_xor_sync(0xffffffffu, wv.y, m);
        wv.z += __shfl_xor_sync(0xffffffffu, wv.z, m);
        wv.w += __shfl_xor_sync(0xffffffffu, wv.w, m);
    }

    if (lane < 4)
        *reinterpret_cast<float4*>(out + n * 16 + lane * 4) = wv;
}

// ------------------------------------------------------------------
extern "C" void kernel_launch(void* const* d_in, const int* in_sizes, int n_in,
                              void* d_out, int out_size)
{
    const float* h  = (const float*)d_in[0];
    const float* Qw = (const float*)d_in[1];
    const float* Qb = (const float*)d_in[2];
    const float* Kw = (const float*)d_in[3];
    const float* Kb = (const float*)d_in[4];
    const float* Vw = (const float*)d_in[5];
    const float* Vb = (const float*)d_in[6];
    const int*  src = (const int*) d_in[7];
    const int*  dst = (const int*) d_in[8];
    float* out = (float*)d_out;

    int N  = in_sizes[0] / INDIM;
    int nE = in_sizes[7];

    prep_kernel<<<(128 * 128 + 255) / 256, 256>>>(Qw, Qb, Kw, Kb, Vw, Vb);
    zero_kernel<<<(N * 32 + 255) / 256, 256>>>(N);

    dim3 ggrid((N + BM - 1) / BM, (OCOLS + BN - 1) / BN);
    gemm_kernel<<<ggrid, 256>>>(h, N);

    int warps = (nE + EPW - 1) / EPW;
    int eblocks = (warps + 7) / 8;
    edge_kernel<<<eblocks, 256>>>(src, dst, nE);

    int fblocks = (N + 7) / 8;
    final_kernel<<<fblocks, 256>>>(out, N);
}

// round 6
// speedup vs baseline: 2.0650x; 1.1079x over previous
#include <cuda_runtime.h>
#include <cuda_fp16.h>
#include <math.h>

#define MAXN 50048
#define MAXE 1605632
#define NH 8
#define OD 16

// ---- device scratch ----
__device__ __half g_KV [MAXN * 256];    // [node][K(128) | V(128)] fp16
__device__ float  g_Qs [MAXN * 16];     // Qsum fp32
__device__ float  g_W  [256 * 128];     // Kw | Vw
__device__ float  g_b  [256];
__device__ float  g_Qsw[16 * 128];      // head-reduced Q weights
__device__ float  g_qb [16];
__device__ int    g_cnt[MAXN];
__device__ int    g_cur[MAXN];
__device__ int    g_ofs[MAXN + 1];
__device__ int    g_part[256];
__device__ int    g_adj[MAXE];

// ------------------------------------------------------------------
// Kernel: assemble weights
// ------------------------------------------------------------------
__global__ void prep_kernel(const float* __restrict__ Qw, const float* __restrict__ Qb,
                            const float* __restrict__ Kw, const float* __restrict__ Kb,
                            const float* __restrict__ Vw, const float* __restrict__ Vb)
{
    int t = blockIdx.x * blockDim.x + threadIdx.x;
    if (t < 128 * 128) {
        g_W[t]             = Kw[t];
        g_W[128 * 128 + t] = Vw[t];
    }
    if (t < 16 * 128) {
        int d = t / 128, c = t % 128;
        float s = 0.f;
        #pragma unroll
        for (int hh = 0; hh < NH; hh++) s += Qw[(hh * OD + d) * 128 + c];
        g_Qsw[t] = s;
    }
    if (t < 128) { g_b[t] = Kb[t]; g_b[128 + t] = Vb[t]; }
    if (t < 16) {
        float s = 0.f;
        #pragma unroll
        for (int hh = 0; hh < NH; hh++) s += Qb[hh * OD + t];
        g_qb[t] = s;
    }
}

// ------------------------------------------------------------------
// Kernel: zero CSR counters
// ------------------------------------------------------------------
__global__ void zero_cnt_kernel(int N)
{
    int i = blockIdx.x * blockDim.x + threadIdx.x;
    if (i < N) { g_cnt[i] = 0; g_cur[i] = 0; }
}

// ------------------------------------------------------------------
// Kernel: GEMM  C[N,256] = h @ [Kw|Vw]^T + b  -> fp16 g_KV
// 128x128 tile, BK=8, 8x8 micro-tile, packed fma.rn.f32x2 (FFMA2)
// ------------------------------------------------------------------
#define BM 128
#define BN 128
#define BK 8
__global__ __launch_bounds__(256) void gemm_kernel(const float* __restrict__ h, int N)
{
    __shared__ __align__(16) float As[BK][BM + 4];
    __shared__ __align__(16) float Bs[BK][BN + 4];

    int tid = threadIdx.x;
    int tx = tid & 15;
    int ty = tid >> 4;
    int n0 = blockIdx.x * BM;
    int o0 = blockIdx.y * BN;

    int lrow = tid >> 1;
    int lk   = (tid & 1) * 4;

    unsigned long long acc2[8][4];
    #pragma unroll
    for (int i = 0; i < 8; i++)
        #pragma unroll
        for (int jj = 0; jj < 4; jj++) acc2[i][jj] = 0ull;

    int an = n0 + lrow; if (an >= N) an = N - 1;
    const float* aptr = h   + (size_t)an * 128 + lk;
    const float* bptr = g_W + (size_t)(o0 + lrow) * 128 + lk;

    for (int k0 = 0; k0 < 128; k0 += BK) {
        float4 av = *reinterpret_cast<const float4*>(aptr + k0);
        float4 bv = *reinterpret_cast<const float4*>(bptr + k0);
        As[lk + 0][lrow] = av.x; As[lk + 1][lrow] = av.y;
        As[lk + 2][lrow] = av.z; As[lk + 3][lrow] = av.w;
        Bs[lk + 0][lrow] = bv.x; Bs[lk + 1][lrow] = bv.y;
        Bs[lk + 2][lrow] = bv.z; Bs[lk + 3][lrow] = bv.w;
        __syncthreads();

        #pragma unroll
        for (int kk = 0; kk < BK; kk++) {
            float4 a0 = *reinterpret_cast<const float4*>(&As[kk][ty * 4]);
            float4 a1 = *reinterpret_cast<const float4*>(&As[kk][64 + ty * 4]);
            ulonglong2 bA = *reinterpret_cast<const ulonglong2*>(&Bs[kk][tx * 4]);
            ulonglong2 bB = *reinterpret_cast<const ulonglong2*>(&Bs[kk][64 + tx * 4]);
            unsigned long long B2[4] = { bA.x, bA.y, bB.x, bB.y };
            float aval[8] = { a0.x, a0.y, a0.z, a0.w, a1.x, a1.y, a1.z, a1.w };
            unsigned long long A2[8];
            #pragma unroll
            for (int i = 0; i < 8; i++)
                asm("mov.b64 %0, {%1, %1};" : "=l"(A2[i]) : "f"(aval[i]));
            #pragma unroll
            for (int i = 0; i < 8; i++)
                #pragma unroll
                for (int jj = 0; jj < 4; jj++)
                    asm("fma.rn.f32x2 %0, %1, %2, %0;"
                        : "+l"(acc2[i][jj]) : "l"(A2[i]), "l"(B2[jj]));
        }
        __syncthreads();
    }

    #pragma unroll
    for (int i = 0; i < 8; i++) {
        int n = n0 + ((i < 4) ? (ty * 4 + i) : (64 + ty * 4 + (i - 4)));
        if (n >= N) continue;
        #pragma unroll
        for (int jj = 0; jj < 4; jj++) {
            int jb = (jj < 2) ? (tx * 4 + 2 * jj) : (64 + tx * 4 + 2 * (jj - 2));
            int o = o0 + jb;
            float lo, hi;
            asm("mov.b64 {%0, %1}, %2;" : "=f"(lo), "=f"(hi) : "l"(acc2[i][jj]));
            lo += g_b[o];
            hi += g_b[o + 1];
            *reinterpret_cast<__half2*>(&g_KV[(size_t)n * 256 + o]) =
                __floats2half2_rn(lo, hi);
        }
    }
}

// ------------------------------------------------------------------
// Kernel: Qsum[N,16] = h @ Qsw^T + qb   (16 nodes per 256-thread block)
// ------------------------------------------------------------------
__global__ __launch_bounds__(256) void qs_kernel(const float* __restrict__ h, int N)
{
    __shared__ __align__(16) float W[16 * 128];
    int tid = threadIdx.x;
    for (int t = tid; t < 16 * 128; t += 256) W[t] = g_Qsw[t];
    __syncthreads();

    int node = blockIdx.x * 16 + (tid >> 4);
    int dim  = tid & 15;
    if (node >= N) return;

    float acc = g_qb[dim];
    const float* hp = h + (size_t)node * 128;
    const float* wp = W + dim * 128;
    #pragma unroll
    for (int k = 0; k < 128; k += 4) {
        float4 hv = *reinterpret_cast<const float4*>(hp + k);
        float4 wv = *reinterpret_cast<const float4*>(wp + k);
        acc += hv.x * wv.x + hv.y * wv.y + hv.z * wv.z + hv.w * wv.w;
    }
    g_Qs[node * 16 + dim] = acc;
}

// ------------------------------------------------------------------
// CSR build
// ------------------------------------------------------------------
__global__ void count_kernel(const int* __restrict__ dst, int nE)
{
    int e = blockIdx.x * blockDim.x + threadIdx.x;
    if (e < nE) atomicAdd(&g_cnt[dst[e]], 1);
}

__global__ void scan_a_kernel(int N)
{
    __shared__ int sm[256];
    int tid = threadIdx.x;
    int i = blockIdx.x * 256 + tid;
    int v = (i < N) ? g_cnt[i] : 0;
    sm[tid] = v; __syncthreads();
    #pragma unroll
    for (int off = 1; off < 256; off <<= 1) {
        int t = (tid >= off) ? sm[tid - off] : 0;
        __syncthreads();
        sm[tid] += t;
        __syncthreads();
    }
    if (i < N) g_ofs[i] = sm[tid] - v;               // block-local exclusive
    if (tid == 255) g_part[blockIdx.x] = sm[255];    // block total
}

__global__ void scan_b_kernel(int nb)
{
    __shared__ int sm[256];
    int tid = threadIdx.x;
    int v = (tid < nb) ? g_part[tid] : 0;
    sm[tid] = v; __syncthreads();
    #pragma unroll
    for (int off = 1; off < 256; off <<= 1) {
        int t = (tid >= off) ? sm[tid - off] : 0;
        __syncthreads();
        sm[tid] += t;
        __syncthreads();
    }
    if (tid < nb) g_part[tid] = sm[tid] - v;         // exclusive
}

__global__ void scan_c_kernel(int N, int nE)
{
    int i = blockIdx.x * 256 + threadIdx.x;
    if (i < N) g_ofs[i] += g_part[blockIdx.x];
    if (i == 0) g_ofs[N] = nE;
}

__global__ void fill_kernel(const int* __restrict__ src, const int* __restrict__ dst, int nE)
{
    int e = blockIdx.x * blockDim.x + threadIdx.x;
    if (e < nE) {
        int d = dst[e];
        int p = g_ofs[d] + atomicAdd(&g_cur[d], 1);
        g_adj[p] = src[e];
    }
}

// ------------------------------------------------------------------
// Gather: one warp per dst node. Register accumulation, no atomics.
// Fuses edge pass + self-loop + normalize + head-mean + output.
// ------------------------------------------------------------------
__device__ __forceinline__ void edge_proc(int s, const float4& q, int lane,
                                          float4& wv, float& z)
{
    const __half* base = g_KV + (size_t)s * 256;
    uint2 kr = *reinterpret_cast<const uint2*>(base + lane * 4);
    uint2 vr = *reinterpret_cast<const uint2*>(base + 128 + lane * 4);

    float2 k0 = __half22float2(*reinterpret_cast<__half2*>(&kr.x));
    float2 k1 = __half22float2(*reinterpret_cast<__half2*>(&kr.y));
    float p = k0.x * q.x + k0.y * q.y + k1.x * q.z + k1.y * q.w;
    p += __shfl_xor_sync(0xffffffffu, p, 1);
    p += __shfl_xor_sync(0xffffffffu, p, 2);
    float sc = __expf(fminf(fmaxf(p * 0.25f, -5.f), 5.f));

    float2 v0 = __half22float2(*reinterpret_cast<__half2*>(&vr.x));
    float2 v1 = __half22float2(*reinterpret_cast<__half2*>(&vr.y));
    wv.x = fmaf(sc, v0.x, wv.x);
    wv.y = fmaf(sc, v0.y, wv.y);
    wv.z = fmaf(sc, v1.x, wv.z);
    wv.w = fmaf(sc, v1.y, wv.w);
    z += sc;
}

__global__ __launch_bounds__(256) void gather_kernel(float* __restrict__ out, int N)
{
    int n    = (blockIdx.x * blockDim.x + threadIdx.x) >> 5;
    int lane = threadIdx.x & 31;
    if (n >= N) return;

    float4 q = *reinterpret_cast<const float4*>(g_Qs + n * 16 + (lane & 3) * 4);
    float4 wv = make_float4(0.f, 0.f, 0.f, 0.f);
    float z = 0.f;

    edge_proc(n, q, lane, wv, z);   // self-loop

    int beg = g_ofs[n], end = g_ofs[n + 1];
    for (int base = beg; base < end; base += 32) {
        int rem = end - base;
        int sv = (lane < rem) ? g_adj[base + lane] : 0;
        int m = min(rem, 32);
        #pragma unroll 4
        for (int i = 0; i < m; i++) {
            int s = __shfl_sync(0xffffffffu, sv, i);
            edge_proc(s, q, lane, wv, z);
        }
    }

    float inv = 0.125f / z;                 // 1/z and mean over 8 heads
    wv.x *= inv; wv.y *= inv; wv.z *= inv; wv.w *= inv;

    #pragma unroll
    for (int m = 4; m < 32; m <<= 1) {
        wv.x += __shfl_xor_sync(0xffffffffu, wv.x, m);
        wv.y += __shfl_xor_sync(0xffffffffu, wv.y, m);
        wv.z += __shfl_xor_sync(0xffffffffu, wv.z, m);
        wv.w += __shfl_xor_sync(0xffffffffu, wv.w, m);
    }

    if (lane < 4)
        *reinterpret_cast<float4*>(out + n * 16 + lane * 4) = wv;
}

// ------------------------------------------------------------------
extern "C" void kernel_launch(void* const* d_in, const int* in_sizes, int n_in,
                              void* d_out, int out_size)
{
    const float* h  = (const float*)d_in[0];
    const float* Qw = (const float*)d_in[1];
    const float* Qb = (const float*)d_in[2];
    const float* Kw = (const float*)d_in[3];
    const float* Kb = (const float*)d_in[4];
    const float* Vw = (const float*)d_in[5];
    const float* Vb = (const float*)d_in[6];
    const int*  src = (const int*) d_in[7];
    const int*  dst = (const int*) d_in[8];
    float* out = (float*)d_out;

    int N  = in_sizes[0] / 128;
    int nE = in_sizes[7];
    int nb = (N + 255) / 256;

    prep_kernel<<<64, 256>>>(Qw, Qb, Kw, Kb, Vw, Vb);
    zero_cnt_kernel<<<nb, 256>>>(N);

    dim3 ggrid((N + BM - 1) / BM, 2);
    gemm_kernel<<<ggrid, 256>>>(h, N);
    qs_kernel<<<(N + 15) / 16, 256>>>(h, N);

    count_kernel<<<(nE + 255) / 256, 256>>>(dst, nE);
    scan_a_kernel<<<nb, 256>>>(N);
    scan_b_kernel<<<1, 256>>>(nb);
    scan_c_kernel<<<nb, 256>>>(N, nE);
    fill_kernel<<<(nE + 255) / 256, 256>>>(src, dst, nE);

    gather_kernel<<<(N + 7) / 8, 256>>>(out, N);
}

// round 7
// speedup vs baseline: 2.7397x; 1.3267x over previous
#include <cuda_runtime.h>
#include <cuda_fp16.h>
#include <math.h>

#define MAXN 50048
#define MAXE 1605632
#define NH 8
#define OD 16

// ---- device scratch ----
__device__ __half g_KV [MAXN * 256];    // [node][K(128) | V(128)] fp16
__device__ float  g_Qs [MAXN * 16];     // Qsum fp32
__device__ float  g_W  [256 * 128];     // Kw | Vw
__device__ float  g_b  [256];
__device__ float  g_Qsw[16 * 128];      // head-reduced Q weights
__device__ float  g_qb [16];
__device__ int    g_cnt[MAXN];
__device__ int    g_cur[MAXN];
__device__ int    g_ofs[MAXN + 1];
__device__ int    g_part[256];
__device__ int    g_adj[MAXE];

// ------------------------------------------------------------------
// Kernel: assemble weights
// ------------------------------------------------------------------
__global__ void prep_kernel(const float* __restrict__ Qw, const float* __restrict__ Qb,
                            const float* __restrict__ Kw, const float* __restrict__ Kb,
                            const float* __restrict__ Vw, const float* __restrict__ Vb)
{
    int t = blockIdx.x * blockDim.x + threadIdx.x;
    if (t < 128 * 128) {
        g_W[t]             = Kw[t];
        g_W[128 * 128 + t] = Vw[t];
    }
    if (t < 16 * 128) {
        int d = t / 128, c = t % 128;
        float s = 0.f;
        #pragma unroll
        for (int hh = 0; hh < NH; hh++) s += Qw[(hh * OD + d) * 128 + c];
        g_Qsw[t] = s;
    }
    if (t < 128) { g_b[t] = Kb[t]; g_b[128 + t] = Vb[t]; }
    if (t < 16) {
        float s = 0.f;
        #pragma unroll
        for (int hh = 0; hh < NH; hh++) s += Qb[hh * OD + t];
        g_qb[t] = s;
    }
}

// ------------------------------------------------------------------
// Kernel: zero CSR counters
// ------------------------------------------------------------------
__global__ void zero_cnt_kernel(int N)
{
    int i = blockIdx.x * blockDim.x + threadIdx.x;
    if (i < N) { g_cnt[i] = 0; g_cur[i] = 0; }
}

// ------------------------------------------------------------------
// Kernel: GEMM  C[N,256] = h @ [Kw|Vw]^T + b  -> fp16 g_KV
// 128x128 tile, BK=8, 8x8 micro-tile, packed fma.rn.f32x2 (FFMA2)
// ------------------------------------------------------------------
#define BM 128
#define BN 128
#define BK 8
__global__ __launch_bounds__(256) void gemm_kernel(const float* __restrict__ h, int N)
{
    __shared__ __align__(16) float As[BK][BM + 4];
    __shared__ __align__(16) float Bs[BK][BN + 4];

    int tid = threadIdx.x;
    int tx = tid & 15;
    int ty = tid >> 4;
    int n0 = blockIdx.x * BM;
    int o0 = blockIdx.y * BN;

    int lrow = tid >> 1;
    int lk   = (tid & 1) * 4;

    unsigned long long acc2[8][4];
    #pragma unroll
    for (int i = 0; i < 8; i++)
        #pragma unroll
        for (int jj = 0; jj < 4; jj++) acc2[i][jj] = 0ull;

    int an = n0 + lrow; if (an >= N) an = N - 1;
    const float* aptr = h   + (size_t)an * 128 + lk;
    const float* bptr = g_W + (size_t)(o0 + lrow) * 128 + lk;

    for (int k0 = 0; k0 < 128; k0 += BK) {
        float4 av = *reinterpret_cast<const float4*>(aptr + k0);
        float4 bv = *reinterpret_cast<const float4*>(bptr + k0);
        As[lk + 0][lrow] = av.x; As[lk + 1][lrow] = av.y;
        As[lk + 2][lrow] = av.z; As[lk + 3][lrow] = av.w;
        Bs[lk + 0][lrow] = bv.x; Bs[lk + 1][lrow] = bv.y;
        Bs[lk + 2][lrow] = bv.z; Bs[lk + 3][lrow] = bv.w;
        __syncthreads();

        #pragma unroll
        for (int kk = 0; kk < BK; kk++) {
            float4 a0 = *reinterpret_cast<const float4*>(&As[kk][ty * 4]);
            float4 a1 = *reinterpret_cast<const float4*>(&As[kk][64 + ty * 4]);
            ulonglong2 bA = *reinterpret_cast<const ulonglong2*>(&Bs[kk][tx * 4]);
            ulonglong2 bB = *reinterpret_cast<const ulonglong2*>(&Bs[kk][64 + tx * 4]);
            unsigned long long B2[4] = { bA.x, bA.y, bB.x, bB.y };
            float aval[8] = { a0.x, a0.y, a0.z, a0.w, a1.x, a1.y, a1.z, a1.w };
            unsigned long long A2[8];
            #pragma unroll
            for (int i = 0; i < 8; i++)
                asm("mov.b64 %0, {%1, %1};" : "=l"(A2[i]) : "f"(aval[i]));
            #pragma unroll
            for (int i = 0; i < 8; i++)
                #pragma unroll
                for (int jj = 0; jj < 4; jj++)
                    asm("fma.rn.f32x2 %0, %1, %2, %0;"
                        : "+l"(acc2[i][jj]) : "l"(A2[i]), "l"(B2[jj]));
        }
        __syncthreads();
    }

    #pragma unroll
    for (int i = 0; i < 8; i++) {
        int n = n0 + ((i < 4) ? (ty * 4 + i) : (64 + ty * 4 + (i - 4)));
        if (n >= N) continue;
        #pragma unroll
        for (int jj = 0; jj < 4; jj++) {
            int jb = (jj < 2) ? (tx * 4 + 2 * jj) : (64 + tx * 4 + 2 * (jj - 2));
            int o = o0 + jb;
            float lo, hi;
            asm("mov.b64 {%0, %1}, %2;" : "=f"(lo), "=f"(hi) : "l"(acc2[i][jj]));
            lo += g_b[o];
            hi += g_b[o + 1];
            *reinterpret_cast<__half2*>(&g_KV[(size_t)n * 256 + o]) =
                __floats2half2_rn(lo, hi);
        }
    }
}

// ------------------------------------------------------------------
// Kernel: Qsum[N,16] = h @ Qsw^T + qb   (16 nodes per 256-thread block)
// W padded to stride 132: dim d, offset k -> banks (4d+k..+3)%32;
// each 8-lane LDS.128 phase covers all 32 banks -> conflict-free.
// ------------------------------------------------------------------
#define QSTRIDE 132
__global__ __launch_bounds__(256) void qs_kernel(const float* __restrict__ h, int N)
{
    __shared__ __align__(16) float W[16 * QSTRIDE];
    int tid = threadIdx.x;
    for (int t = tid; t < 16 * 128; t += 256) {
        int r = t >> 7, c = t & 127;
        W[r * QSTRIDE + c] = g_Qsw[t];
    }
    __syncthreads();

    int node = blockIdx.x * 16 + (tid >> 4);
    int dim  = tid & 15;
    if (node >= N) return;

    float acc = g_qb[dim];
    const float* hp = h + (size_t)node * 128;
    const float* wp = W + dim * QSTRIDE;
    #pragma unroll
    for (int k = 0; k < 128; k += 4) {
        float4 hv = *reinterpret_cast<const float4*>(hp + k);
        float4 wv = *reinterpret_cast<const float4*>(wp + k);
        acc += hv.x * wv.x + hv.y * wv.y + hv.z * wv.z + hv.w * wv.w;
    }
    g_Qs[node * 16 + dim] = acc;
}

// ------------------------------------------------------------------
// CSR build
// ------------------------------------------------------------------
__global__ void count_kernel(const int* __restrict__ dst, int nE)
{
    int e = blockIdx.x * blockDim.x + threadIdx.x;
    if (e < nE) atomicAdd(&g_cnt[dst[e]], 1);
}

__global__ void scan_a_kernel(int N)
{
    __shared__ int sm[256];
    int tid = threadIdx.x;
    int i = blockIdx.x * 256 + tid;
    int v = (i < N) ? g_cnt[i] : 0;
    sm[tid] = v; __syncthreads();
    #pragma unroll
    for (int off = 1; off < 256; off <<= 1) {
        int t = (tid >= off) ? sm[tid - off] : 0;
        __syncthreads();
        sm[tid] += t;
        __syncthreads();
    }
    if (i < N) g_ofs[i] = sm[tid] - v;               // block-local exclusive
    if (tid == 255) g_part[blockIdx.x] = sm[255];    // block total
}

__global__ void scan_b_kernel(int nb)
{
    __shared__ int sm[256];
    int tid = threadIdx.x;
    int v = (tid < nb) ? g_part[tid] : 0;
    sm[tid] = v; __syncthreads();
    #pragma unroll
    for (int off = 1; off < 256; off <<= 1) {
        int t = (tid >= off) ? sm[tid - off] : 0;
        __syncthreads();
        sm[tid] += t;
        __syncthreads();
    }
    if (tid < nb) g_part[tid] = sm[tid] - v;         // exclusive
}

__global__ void scan_c_kernel(int N, int nE)
{
    int i = blockIdx.x * 256 + threadIdx.x;
    if (i < N) g_ofs[i] += g_part[blockIdx.x];
    if (i == 0) g_ofs[N] = nE;
}

__global__ void fill_kernel(const int* __restrict__ src, const int* __restrict__ dst, int nE)
{
    int e = blockIdx.x * blockDim.x + threadIdx.x;
    if (e < nE) {
        int d = dst[e];
        int p = g_ofs[d] + atomicAdd(&g_cur[d], 1);
        g_adj[p] = src[e];
    }
}

// ------------------------------------------------------------------
// Gather: one warp per dst node. Register accumulation, no atomics.
// ------------------------------------------------------------------
__device__ __forceinline__ void edge_proc(int s, const float4& q, int lane,
                                          float4& wv, float& z)
{
    const __half* base = g_KV + (size_t)s * 256;
    uint2 kr = *reinterpret_cast<const uint2*>(base + lane * 4);
    uint2 vr = *reinterpret_cast<const uint2*>(base + 128 + lane * 4);

    float2 k0 = __half22float2(*reinterpret_cast<__half2*>(&kr.x));
    float2 k1 = __half22float2(*reinterpret_cast<__half2*>(&kr.y));
    float p = k0.x * q.x + k0.y * q.y + k1.x * q.z + k1.y * q.w;
    p += __shfl_xor_sync(0xffffffffu, p, 1);
    p += __shfl_xor_sync(0xffffffffu, p, 2);
    float sc = __expf(fminf(fmaxf(p * 0.25f, -5.f), 5.f));

    float2 v0 = __half22float2(*reinterpret_cast<__half2*>(&vr.x));
    float2 v1 = __half22float2(*reinterpret_cast<__half2*>(&vr.y));
    wv.x = fmaf(sc, v0.x, wv.x);
    wv.y = fmaf(sc, v0.y, wv.y);
    wv.z = fmaf(sc, v1.x, wv.z);
    wv.w = fmaf(sc, v1.y, wv.w);
    z += sc;
}

__global__ __launch_bounds__(256) void gather_kernel(float* __restrict__ out, int N)
{
    int n    = (blockIdx.x * blockDim.x + threadIdx.x) >> 5;
    int lane = threadIdx.x & 31;
    if (n >= N) return;

    float4 q = *reinterpret_cast<const float4*>(g_Qs + n * 16 + (lane & 3) * 4);
    float4 wv = make_float4(0.f, 0.f, 0.f, 0.f);
    float z = 0.f;

    edge_proc(n, q, lane, wv, z);   // self-loop

    int beg = g_ofs[n], end = g_ofs[n + 1];
    for (int base = beg; base < end; base += 32) {
        int rem = end - base;
        int sv = (lane < rem) ? g_adj[base + lane] : 0;
        int m = min(rem, 32);
        #pragma unroll 4
        for (int i = 0; i < m; i++) {
            int s = __shfl_sync(0xffffffffu, sv, i);
            edge_proc(s, q, lane, wv, z);
        }
    }

    float inv = 0.125f / z;
    wv.x *= inv; wv.y *= inv; wv.z *= inv; wv.w *= inv;

    #pragma unroll
    for (int m = 4; m < 32; m <<= 1) {
        wv.x += __shfl_xor_sync(0xffffffffu, wv.x, m);
        wv.y += __shfl_xor_sync(0xffffffffu, wv.y, m);
        wv.z += __shfl_xor_sync(0xffffffffu, wv.z, m);
        wv.w += __shfl_xor_sync(0xffffffffu, wv.w, m);
    }

    if (lane < 4)
        *reinterpret_cast<float4*>(out + n * 16 + lane * 4) = wv;
}

// ------------------------------------------------------------------
extern "C" void kernel_launch(void* const* d_in, const int* in_sizes, int n_in,
                              void* d_out, int out_size)
{
    const float* h  = (const float*)d_in[0];
    const float* Qw = (const float*)d_in[1];
    const float* Qb = (const float*)d_in[2];
    const float* Kw = (const float*)d_in[3];
    const float* Kb = (const float*)d_in[4];
    const float* Vw = (const float*)d_in[5];
    const float* Vb = (const float*)d_in[6];
    const int*  src = (const int*) d_in[7];
    const int*  dst = (const int*) d_in[8];
    float* out = (float*)d_out;

    int N  = in_sizes[0] / 128;
    int nE = in_sizes[7];
    int nb = (N + 255) / 256;

    prep_kernel<<<64, 256>>>(Qw, Qb, Kw, Kb, Vw, Vb);
    zero_cnt_kernel<<<nb, 256>>>(N);

    dim3 ggrid((N + BM - 1) / BM, 2);
    gemm_kernel<<<ggrid, 256>>>(h, N);
    qs_kernel<<<(N + 15) / 16, 256>>>(h, N);

    count_kernel<<<(nE + 255) / 256, 256>>>(dst, nE);
    scan_a_kernel<<<nb, 256>>>(N);
    scan_b_kernel<<<1, 256>>>(nb);
    scan_c_kernel<<<nb, 256>>>(N, nE);
    fill_kernel<<<(nE + 255) / 256, 256>>>(src, dst, nE);

    gather_kernel<<<(N + 7) / 8, 256>>>(out, N);
}